// round 1
// baseline (speedup 1.0000x reference)
#include <cuda_runtime.h>
#include <math.h>

#define NPIX 262144      // 16*128*128
#define DIMD 64
#define KC   1024
#define NCELL 8192
#define XLO  (-12.0)
#define XRNG (24.0)
#define CWID (XRNG / (double)NCELL)
#define PADX (1e-4)
#define EPSM (1e-4f)

// ---- scratch (__device__ globals; no allocation) ----
__device__ double d_m[KC], d_g[KC];          // line slope/intercept (fp64)
__device__ float  d_mf[KC], d_gf[KC];        // fp32 copies for scans
__device__ float  d_of[KC];                  // o_k = emb_k . w_out
__device__ double d_Sw, d_Swb, d_Sb;         // sum w^2, w*b, b^2
__device__ int    d_cnt[NCELL];
__device__ int    d_cand[NCELL * 8];
__device__ double d_bsum[NPIX / 256];        // per-block loss partial sums

// ================= K1: per-code line precompute =================
__global__ void k_lines(const float* __restrict__ emb,
                        const float* __restrict__ w_in,
                        const float* __restrict__ b_in,
                        const float* __restrict__ w_out) {
    int k = blockIdx.x * blockDim.x + threadIdx.x;
    if (k < KC) {
        const float* e = emb + k * DIMD;
        double a = 0.0, c = 0.0, s = 0.0, o = 0.0;
        #pragma unroll
        for (int d = 0; d < DIMD; ++d) {
            double ed = (double)e[d];
            a += (double)w_in[d]  * ed;
            c += (double)b_in[d]  * ed;
            s += ed * ed;
            o += (double)w_out[d] * ed;
        }
        double m = -2.0 * a;
        double g = s - 2.0 * c;
        d_m[k] = m;  d_g[k] = g;
        d_mf[k] = (float)m;  d_gf[k] = (float)g;
        d_of[k] = (float)o;
    }
    if (blockIdx.x == 0 && threadIdx.x == 0) {
        double sw = 0.0, swb = 0.0, sb = 0.0;
        for (int d = 0; d < DIMD; ++d) {
            double w = (double)w_in[d], bb = (double)b_in[d];
            sw += w * w;  swb += w * bb;  sb += bb * bb;
        }
        d_Sw = sw;  d_Swb = swb;  d_Sb = sb;
    }
}

// ================= K2: per-cell candidate lists =================
__global__ void k_cells() {
    __shared__ float sva[128], svb[128];
    __shared__ int   sia[128], sib[128];
    __shared__ double speak;
    __shared__ int   scnt;
    __shared__ int   scand[8];

    int cell = blockIdx.x;
    int t = threadIdx.x;
    double dxa = XLO + (double)cell * CWID - PADX;
    double dxb = XLO + (double)(cell + 1) * CWID + PADX;
    float xa = (float)dxa, xb = (float)dxb;

    // argmin at both (padded) endpoints, fp32
    float ba = INFINITY, bb = INFINITY;
    int ia = 0, ib = 0;
    for (int j = t; j < KC; j += 128) {
        float m = d_mf[j], g = d_gf[j];
        float va = fmaf(m, xa, g);
        float vb = fmaf(m, xb, g);
        if (va < ba) { ba = va; ia = j; }
        if (vb < bb) { bb = vb; ib = j; }
    }
    sva[t] = ba; sia[t] = ia; svb[t] = bb; sib[t] = ib;
    __syncthreads();
    for (int s = 64; s > 0; s >>= 1) {
        if (t < s) {
            if (sva[t + s] < sva[t]) { sva[t] = sva[t + s]; sia[t] = sia[t + s]; }
            if (svb[t + s] < svb[t]) { svb[t] = svb[t + s]; sib[t] = sib[t + s]; }
        }
        __syncthreads();
    }

    if (t == 0) {
        // sound upper bound on envelope over the cell:
        // E(x) <= min(line_c0(x), line_c1(x))  (min of ANY two lines),
        // peak of that wedge = max(endpoints, crossing if inside).
        int c0 = sia[0], c1 = sib[0];
        double m0 = d_m[c0], g0 = d_g[c0];
        double m1 = d_m[c1], g1 = d_g[c1];
        double wa = fmin(fma(m0, dxa, g0), fma(m1, dxa, g1));
        double wb = fmin(fma(m0, dxb, g0), fma(m1, dxb, g1));
        double pk = fmax(wa, wb);
        if (m0 != m1) {
            double xc = (g1 - g0) / (m0 - m1);
            if (xc > dxa && xc < dxb) pk = fmax(pk, fma(m0, xc, g0));
        }
        speak = pk;
        scnt = 0;
    }
    __syncthreads();

    float pkf = (float)speak + EPSM;
    for (int j = t; j < KC; j += 128) {
        float m = d_mf[j], g = d_gf[j];
        float vm = fminf(fmaf(m, xa, g), fmaf(m, xb, g));
        if (vm <= pkf) {
            int slot = atomicAdd(&scnt, 1);
            if (slot < 8) scand[slot] = j;
        }
    }
    __syncthreads();
    if (t == 0) d_cnt[cell] = scnt;
    if (t < 8 && t < scnt) d_cand[cell * 8 + t] = scand[t];
}

// ================= K3: per-pixel argmin + output + loss =================
__global__ void k_pix(const float* __restrict__ x_in,
                      const float* __restrict__ b_out,
                      float* __restrict__ out) {
    __shared__ double sl[256];
    int p = blockIdx.x * 256 + threadIdx.x;
    float x = x_in[p];
    double xd = (double)x;

    float rel = (x - (float)XLO) * (float)(1.0 / CWID);
    int cell = (int)floorf(rel);
    bool full = (cell < 0) || (cell >= NCELL);
    int cnt = 0;
    if (!full) {
        cnt = d_cnt[cell];
        if (cnt > 8) full = true;
    }

    double best = 1e300;
    int bk = KC;
    if (!full) {
        int base = cell * 8;
        for (int i = 0; i < cnt; ++i) {
            int k = d_cand[base + i];
            double v = fma(d_m[k], xd, d_g[k]);
            if (v < best || (v == best && k < bk)) { best = v; bk = k; }
        }
    } else {
        // exact fallback (never expected for |x| < 12 and sane data)
        for (int k = 0; k < KC; ++k) {
            double v = fma(d_m[k], xd, d_g[k]);
            if (v < best) { best = v; bk = k; }
        }
    }

    out[p] = (float)((double)d_of[bk] + (double)b_out[0]);

    // sum_d (q-h)^2 = best + x^2*Sw + 2x*Swb + Sb
    double lp = best + xd * xd * d_Sw + 2.0 * xd * d_Swb + d_Sb;
    sl[threadIdx.x] = lp;
    __syncthreads();
    for (int s = 128; s > 0; s >>= 1) {
        if (threadIdx.x < s) sl[threadIdx.x] += sl[threadIdx.x + s];
        __syncthreads();
    }
    if (threadIdx.x == 0) d_bsum[blockIdx.x] = sl[0];
}

// ================= K4: deterministic final reduction =================
__global__ void k_fin(float* __restrict__ out, int out_size) {
    __shared__ double s[512];
    int t = threadIdx.x;
    s[t] = d_bsum[t] + d_bsum[t + 512];
    __syncthreads();
    for (int st = 256; st > 0; st >>= 1) {
        if (t < st) s[t] += s[t + st];
        __syncthreads();
    }
    if (t == 0 && out_size > NPIX) {
        // loss = KLD*(CC+1)*mean = 12.5 * sum / (NPIX*D)
        out[NPIX] = (float)(12.5 * s[0] / ((double)NPIX * (double)DIMD));
    }
}

extern "C" void kernel_launch(void* const* d_in, const int* in_sizes, int n_in,
                              void* d_out, int out_size) {
    const float* x     = (const float*)d_in[0];
    const float* w_in  = (const float*)d_in[1];
    const float* b_in  = (const float*)d_in[2];
    const float* emb   = (const float*)d_in[3];
    const float* w_out = (const float*)d_in[4];
    const float* b_out = (const float*)d_in[5];
    float* out = (float*)d_out;

    k_lines<<<8, 128>>>(emb, w_in, b_in, w_out);
    k_cells<<<NCELL, 128>>>();
    k_pix<<<NPIX / 256, 256>>>(x, b_out, out);
    k_fin<<<1, 512>>>(out, out_size);
}

// round 2
// speedup vs baseline: 1.2732x; 1.2732x over previous
#include <cuda_runtime.h>
#include <math.h>

#define NPIX 262144      // 16*128*128
#define DIMD 64
#define KC   1024
#define NFINE 8192
#define NCOARSE 256
#define FPC   (NFINE / NCOARSE)      // 32 fine cells per coarse cell
#define XLO  (-12.0)
#define XRNG (24.0)
#define FWID (XRNG / (double)NFINE)
#define CWID (XRNG / (double)NCOARSE)
#define PADX (1e-4)
#define EPSM (1e-4f)
#define CCAP 64
#define FCAP 8

// ---- scratch (__device__ globals; no allocation) ----
__device__ double d_m[KC], d_g[KC];          // line slope/intercept (fp64)
__device__ float  d_mf[KC], d_gf[KC];        // fp32 copies
__device__ float  d_of[KC];                  // o_k = emb_k . w_out
__device__ float  d_Swf, d_Swbf, d_Sbf;      // fp32 loss-quadratic coeffs
__device__ int    d_cnt[NFINE];
__device__ int    d_cand[NFINE * FCAP];
__device__ double d_bsum[NPIX / 256];        // per-block loss partials

// ================= K1: per-code line precompute =================
__global__ void k_lines(const float* __restrict__ emb,
                        const float* __restrict__ w_in,
                        const float* __restrict__ b_in,
                        const float* __restrict__ w_out) {
    int k = blockIdx.x * blockDim.x + threadIdx.x;
    if (k < KC) {
        const float* e = emb + k * DIMD;
        double a = 0.0, c = 0.0, s = 0.0, o = 0.0;
        #pragma unroll
        for (int d = 0; d < DIMD; ++d) {
            double ed = (double)e[d];
            a += (double)w_in[d]  * ed;
            c += (double)b_in[d]  * ed;
            s += ed * ed;
            o += (double)w_out[d] * ed;
        }
        double m = -2.0 * a;
        double g = s - 2.0 * c;
        d_m[k] = m;  d_g[k] = g;
        d_mf[k] = (float)m;  d_gf[k] = (float)g;
        d_of[k] = (float)o;
    }
    if (blockIdx.x == 0 && threadIdx.x == 0) {
        double sw = 0.0, swb = 0.0, sb = 0.0;
        for (int d = 0; d < DIMD; ++d) {
            double w = (double)w_in[d], bb = (double)b_in[d];
            sw += w * w;  swb += w * bb;  sb += bb * bb;
        }
        d_Swf = (float)sw;  d_Swbf = (float)swb;  d_Sbf = (float)sb;
    }
}

// Sound wedge-peak bound over [xa,xb] from two lines (fp64):
// envelope <= min(L0, L1); peak of the wedge = max(endpoint mins, crossing).
__device__ double wedge_peak(int c0, int c1, double xa, double xb) {
    double m0 = d_m[c0], g0 = d_g[c0];
    double m1 = d_m[c1], g1 = d_g[c1];
    double wa = fmin(fma(m0, xa, g0), fma(m1, xa, g1));
    double wb = fmin(fma(m0, xb, g0), fma(m1, xb, g1));
    double pk = fmax(wa, wb);
    if (m0 != m1) {
        double xc = (g1 - g0) / (m0 - m1);
        if (xc > xa && xc < xb) pk = fmax(pk, fma(m0, xc, g0));
    }
    return pk;
}

// ================= K2: hierarchical cell build =================
// One block per COARSE cell (256 blocks x 256 threads).
// Phase A: scan all 1024 lines once -> coarse candidate list (cap 64).
// Phase B: 8 threads per fine cell scan the coarse list -> fine list (cap 8).
__global__ void __launch_bounds__(256) k_cells2() {
    __shared__ float sva[256], svb[256];
    __shared__ int   sia[256], sib[256];
    __shared__ int   scand[CCAP];
    __shared__ int   scnt;
    __shared__ float speakc;
    __shared__ int   sfcnt[FPC];

    int cc = blockIdx.x;
    int t = threadIdx.x;
    double dxa = XLO + (double)cc * CWID - PADX;
    double dxb = XLO + (double)(cc + 1) * CWID + PADX;
    float xa = (float)dxa, xb = (float)dxb;

    // --- Phase A1: coarse endpoint argmin (each thread: 4 lines) ---
    float ba = INFINITY, bb = INFINITY;
    int ia = 0, ib = 0;
    #pragma unroll
    for (int j = t; j < KC; j += 256) {
        float m = d_mf[j], g = d_gf[j];
        float va = fmaf(m, xa, g);
        float vb = fmaf(m, xb, g);
        if (va < ba) { ba = va; ia = j; }
        if (vb < bb) { bb = vb; ib = j; }
    }
    sva[t] = ba; sia[t] = ia; svb[t] = bb; sib[t] = ib;
    __syncthreads();
    for (int s = 128; s > 0; s >>= 1) {
        if (t < s) {
            if (sva[t + s] < sva[t]) { sva[t] = sva[t + s]; sia[t] = sia[t + s]; }
            if (svb[t + s] < svb[t]) { svb[t] = svb[t + s]; sib[t] = sib[t + s]; }
        }
        __syncthreads();
    }
    if (t == 0) {
        speakc = (float)wedge_peak(sia[0], sib[0], dxa, dxb) + EPSM;
        scnt = 0;
    }
    __syncthreads();

    // --- Phase A2: collect coarse candidates ---
    float pkc = speakc;
    #pragma unroll
    for (int j = t; j < KC; j += 256) {
        float m = d_mf[j], g = d_gf[j];
        float vm = fminf(fmaf(m, xa, g), fmaf(m, xb, g));
        if (vm <= pkc) {
            int slot = atomicAdd(&scnt, 1);
            if (slot < CCAP) scand[slot] = j;
        }
    }
    __syncthreads();
    int ccnt = scnt;
    if (ccnt > CCAP) {
        // overflow: flag all fine cells for full fallback (practically never)
        if (t < FPC) d_cnt[cc * FPC + t] = 9999;
        return;
    }
    if (t < FPC) sfcnt[t] = 0;
    __syncthreads();

    // --- Phase B: fine cells. 8 threads (r) per fine cell (j). ---
    int j = t >> 3;           // fine cell within coarse (0..31)
    int r = t & 7;
    int fcell = cc * FPC + j;
    double fxa = XLO + (double)fcell * FWID - PADX;
    double fxb = XLO + (double)(fcell + 1) * FWID + PADX;
    float fa = (float)fxa, fb = (float)fxb;

    float fba = INFINITY, fbb = INFINITY;
    int fia = 0, fib = 0;
    for (int i = r; i < ccnt; i += 8) {
        int k = scand[i];
        float m = d_mf[k], g = d_gf[k];
        float va = fmaf(m, fa, g);
        float vb = fmaf(m, fb, g);
        if (va < fba) { fba = va; fia = k; }
        if (vb < fbb) { fbb = vb; fib = k; }
    }
    // reduce across the 8 threads of this fine cell (same warp, width 8)
    #pragma unroll
    for (int s = 4; s > 0; s >>= 1) {
        float ova = __shfl_down_sync(0xFFFFFFFFu, fba, s, 8);
        int   oia = __shfl_down_sync(0xFFFFFFFFu, fia, s, 8);
        float ovb = __shfl_down_sync(0xFFFFFFFFu, fbb, s, 8);
        int   oib = __shfl_down_sync(0xFFFFFFFFu, fib, s, 8);
        if (ova < fba) { fba = ova; fia = oia; }
        if (ovb < fbb) { fbb = ovb; fib = oib; }
    }
    float pkf;
    if (r == 0) pkf = (float)wedge_peak(fia, fib, fxa, fxb) + EPSM;
    pkf = __shfl_sync(0xFFFFFFFFu, pkf, (t & ~7) & 31, 32);  // broadcast from r==0 lane

    // collect fine candidates
    for (int i = r; i < ccnt; i += 8) {
        int k = scand[i];
        float m = d_mf[k], g = d_gf[k];
        float vm = fminf(fmaf(m, fa, g), fmaf(m, fb, g));
        if (vm <= pkf) {
            int slot = atomicAdd(&sfcnt[j], 1);
            if (slot < FCAP) d_cand[fcell * FCAP + slot] = k;
        }
    }
    __syncthreads();
    if (r == 0) d_cnt[fcell] = sfcnt[j];
}

// ================= K3: per-pixel argmin + output + loss =================
__global__ void __launch_bounds__(256) k_pix(const float* __restrict__ x_in,
                      const float* __restrict__ b_out,
                      float* __restrict__ out) {
    __shared__ double sl[256];
    int p = blockIdx.x * 256 + threadIdx.x;
    float x = x_in[p];

    float rel = (x - (float)XLO) * (float)(1.0 / FWID);
    int cell = (int)floorf(rel);
    bool full = (cell < 0) || (cell >= NFINE);
    int cnt = 0;
    if (!full) {
        cnt = d_cnt[cell];
        if (cnt > FCAP || cnt <= 0) full = true;
    }

    int bk;
    float bestf;
    if (!full) {
        int base = cell * FCAP;
        if (cnt == 1) {
            bk = d_cand[base];
            bestf = fmaf(d_mf[bk], x, d_gf[bk]);
        } else {
            double xd = (double)x;
            double best = 1e300;
            bk = KC;
            for (int i = 0; i < cnt; ++i) {
                int k = d_cand[base + i];
                double v = fma(d_m[k], xd, d_g[k]);
                if (v < best || (v == best && k < bk)) { best = v; bk = k; }
            }
            bestf = (float)best;
        }
    } else {
        // exact fallback (never expected for |x| < 12)
        double xd = (double)x;
        double best = 1e300;
        bk = KC;
        for (int k = 0; k < KC; ++k) {
            double v = fma(d_m[k], xd, d_g[k]);
            if (v < best) { best = v; bk = k; }
        }
        bestf = (float)best;
    }

    out[p] = d_of[bk] + b_out[0];

    // sum_d (q-h)^2 = best + x^2*Sw + 2x*Swb + Sb   (fp32 per-term is plenty)
    float lp = bestf + fmaf(x, fmaf(x, d_Swf, 2.0f * d_Swbf), d_Sbf);
    sl[threadIdx.x] = (double)lp;
    __syncthreads();
    for (int s = 128; s > 0; s >>= 1) {
        if (threadIdx.x < s) sl[threadIdx.x] += sl[threadIdx.x + s];
        __syncthreads();
    }
    if (threadIdx.x == 0) d_bsum[blockIdx.x] = sl[0];
}

// ================= K4: deterministic final reduction =================
__global__ void k_fin(float* __restrict__ out, int out_size) {
    __shared__ double s[512];
    int t = threadIdx.x;
    s[t] = d_bsum[t] + d_bsum[t + 512];
    __syncthreads();
    for (int st = 256; st > 0; st >>= 1) {
        if (t < st) s[t] += s[t + st];
        __syncthreads();
    }
    if (t == 0 && out_size > NPIX) {
        // loss = KLD*(CC+1)*mean = 12.5 * sum / (NPIX*D)
        out[NPIX] = (float)(12.5 * s[0] / ((double)NPIX * (double)DIMD));
    }
}

extern "C" void kernel_launch(void* const* d_in, const int* in_sizes, int n_in,
                              void* d_out, int out_size) {
    const float* x     = (const float*)d_in[0];
    const float* w_in  = (const float*)d_in[1];
    const float* b_in  = (const float*)d_in[2];
    const float* emb   = (const float*)d_in[3];
    const float* w_out = (const float*)d_in[4];
    const float* b_out = (const float*)d_in[5];
    float* out = (float*)d_out;

    k_lines<<<8, 128>>>(emb, w_in, b_in, w_out);
    k_cells2<<<NCOARSE, 256>>>();
    k_pix<<<NPIX / 256, 256>>>(x, b_out, out);
    k_fin<<<1, 512>>>(out, out_size);
}

// round 3
// speedup vs baseline: 2.4303x; 1.9088x over previous
#include <cuda_runtime.h>
#include <math.h>

#define NPIX 262144      // 16*128*128
#define DIMD 64
#define KC   1024
#define NFINE 8192
#define NCOARSE 256
#define FPC   (NFINE / NCOARSE)      // 32 fine cells per coarse cell
#define XLO  (-12.0)
#define XRNG (24.0)
#define FWID (XRNG / (double)NFINE)
#define CWID (XRNG / (double)NCOARSE)
#define PADX (1e-4)
#define EPSM (1e-4f)
#define CCAP 64
#define FCAP 8
#define NBLKB 256                    // kB blocks (256*256 threads*4 pix = NPIX)

// ---- scratch (__device__ globals; zero-initialized at module load) ----
__device__ double d_m[KC], d_g[KC];          // line slope/intercept (fp64)
__device__ float  d_mf[KC], d_gf[KC];        // fp32 copies
__device__ float  d_of[KC];                  // o_k = emb_k . w_out
__device__ float  d_Swf, d_Swbf, d_Sbf;      // loss-quadratic coeffs
__device__ int    d_cand[NFINE * FCAP];      // slow-path candidate lists
__device__ float4 d_fast[NFINE];             // (m, g, o, cnt-as-int) per fine cell
__device__ double d_bsum[NBLKB];             // per-block loss partials
__device__ unsigned d_barA;                  // kA grid barrier (reset by kB)
__device__ unsigned d_doneB;                 // kB last-block counter (reset by kA)

// Sound wedge-peak bound over [xa,xb] from two lines (fp64):
// envelope <= min(L0, L1); peak of that wedge = max(endpoint mins, crossing).
__device__ double wedge_peak(int c0, int c1, double xa, double xb) {
    double m0 = d_m[c0], g0 = d_g[c0];
    double m1 = d_m[c1], g1 = d_g[c1];
    double wa = fmin(fma(m0, xa, g0), fma(m1, xa, g1));
    double wb = fmin(fma(m0, xb, g0), fma(m1, xb, g1));
    double pk = fmax(wa, wb);
    if (m0 != m1) {
        double xc = (g1 - g0) / (m0 - m1);
        if (xc > xa && xc < xb) pk = fmax(pk, fma(m0, xc, g0));
    }
    return pk;
}

// ================= kA: lines + grid barrier + cell build =================
__global__ void __launch_bounds__(256) kA(const float* __restrict__ emb,
                                          const float* __restrict__ w_in,
                                          const float* __restrict__ b_in,
                                          const float* __restrict__ w_out) {
    __shared__ float smf[KC], sgf[KC];
    __shared__ float sva[256], svb[256];
    __shared__ int   sia[256], sib[256];
    __shared__ int   scand[CCAP];
    __shared__ int   scnt;
    __shared__ float speakc;
    __shared__ int   sfcnt[FPC];

    int cc = blockIdx.x;
    int t  = threadIdx.x;
    int w  = t >> 5, lane = t & 31;

    if (cc == 0 && t == 0) d_doneB = 0;   // arm kB's last-block counter

    // --- Phase 1: this block computes lines cc*4 .. cc*4+3 (warp per line) ---
    if (w < 4) {
        int k = cc * 4 + w;
        const float* e = emb + k * DIMD;
        double a = 0.0, c = 0.0, s = 0.0, o = 0.0;
        #pragma unroll
        for (int d = lane; d < DIMD; d += 32) {
            double ed = (double)e[d];
            a += (double)w_in[d]  * ed;
            c += (double)b_in[d]  * ed;
            s += ed * ed;
            o += (double)w_out[d] * ed;
        }
        #pragma unroll
        for (int off = 16; off; off >>= 1) {
            a += __shfl_down_sync(0xFFFFFFFFu, a, off);
            c += __shfl_down_sync(0xFFFFFFFFu, c, off);
            s += __shfl_down_sync(0xFFFFFFFFu, s, off);
            o += __shfl_down_sync(0xFFFFFFFFu, o, off);
        }
        if (lane == 0) {
            double m = -2.0 * a, g = s - 2.0 * c;
            d_m[k] = m;  d_g[k] = g;
            d_mf[k] = (float)m;  d_gf[k] = (float)g;
            d_of[k] = (float)o;
        }
    } else if (cc == 0 && w == 4) {
        double sw = 0.0, swb = 0.0, sb = 0.0;
        for (int d = lane; d < DIMD; d += 32) {
            double ww = (double)w_in[d], bb = (double)b_in[d];
            sw += ww * ww;  swb += ww * bb;  sb += bb * bb;
        }
        #pragma unroll
        for (int off = 16; off; off >>= 1) {
            sw  += __shfl_down_sync(0xFFFFFFFFu, sw,  off);
            swb += __shfl_down_sync(0xFFFFFFFFu, swb, off);
            sb  += __shfl_down_sync(0xFFFFFFFFu, sb,  off);
        }
        if (lane == 0) { d_Swf = (float)sw;  d_Swbf = (float)swb;  d_Sbf = (float)sb; }
    }
    __syncthreads();

    // --- software grid barrier (all 256 blocks co-resident) ---
    if (t == 0) {
        __threadfence();
        atomicAdd(&d_barA, 1);
        while (atomicAdd(&d_barA, 0) < NCOARSE) { }
        __threadfence();
    }
    __syncthreads();

    // --- load all lines into smem ---
    for (int j = t; j < KC; j += 256) { smf[j] = d_mf[j]; sgf[j] = d_gf[j]; }
    __syncthreads();

    // --- Phase A: coarse cell endpoint argmin ---
    double dxa = XLO + (double)cc * CWID - PADX;
    double dxb = XLO + (double)(cc + 1) * CWID + PADX;
    float xa = (float)dxa, xb = (float)dxb;

    float ba = INFINITY, bb = INFINITY;
    int ia = 0, ib = 0;
    #pragma unroll
    for (int j = t; j < KC; j += 256) {
        float m = smf[j], g = sgf[j];
        float va = fmaf(m, xa, g);
        float vb = fmaf(m, xb, g);
        if (va < ba) { ba = va; ia = j; }
        if (vb < bb) { bb = vb; ib = j; }
    }
    sva[t] = ba; sia[t] = ia; svb[t] = bb; sib[t] = ib;
    __syncthreads();
    for (int s = 128; s > 0; s >>= 1) {
        if (t < s) {
            if (sva[t + s] < sva[t]) { sva[t] = sva[t + s]; sia[t] = sia[t + s]; }
            if (svb[t + s] < svb[t]) { svb[t] = svb[t + s]; sib[t] = sib[t + s]; }
        }
        __syncthreads();
    }
    if (t == 0) {
        speakc = (float)wedge_peak(sia[0], sib[0], dxa, dxb) + EPSM;
        scnt = 0;
    }
    __syncthreads();

    // --- Phase A2: collect coarse candidates ---
    float pkc = speakc;
    #pragma unroll
    for (int j = t; j < KC; j += 256) {
        float m = smf[j], g = sgf[j];
        float vm = fminf(fmaf(m, xa, g), fmaf(m, xb, g));
        if (vm <= pkc) {
            int slot = atomicAdd(&scnt, 1);
            if (slot < CCAP) scand[slot] = j;
        }
    }
    __syncthreads();
    int ccnt = scnt;
    if (ccnt > CCAP) {
        // overflow: flag all fine cells for full fallback (practically never)
        if (t < FPC) {
            float4 fv; fv.x = 0.f; fv.y = 0.f; fv.z = 0.f;
            fv.w = __int_as_float(9999);
            d_fast[cc * FPC + t] = fv;
        }
        return;
    }
    if (t < FPC) sfcnt[t] = 0;
    __syncthreads();

    // --- Phase B: fine cells. 8 threads (r) per fine cell (j). ---
    int j = t >> 3;
    int r = t & 7;
    int fcell = cc * FPC + j;
    double fxa = XLO + (double)fcell * FWID - PADX;
    double fxb = XLO + (double)(fcell + 1) * FWID + PADX;
    float fa = (float)fxa, fb = (float)fxb;

    float fba = INFINITY, fbb = INFINITY;
    int fia = 0, fib = 0;
    for (int i = r; i < ccnt; i += 8) {
        int k = scand[i];
        float m = smf[k], g = sgf[k];
        float va = fmaf(m, fa, g);
        float vb = fmaf(m, fb, g);
        if (va < fba) { fba = va; fia = k; }
        if (vb < fbb) { fbb = vb; fib = k; }
    }
    #pragma unroll
    for (int s = 4; s > 0; s >>= 1) {
        float ova = __shfl_down_sync(0xFFFFFFFFu, fba, s, 8);
        int   oia = __shfl_down_sync(0xFFFFFFFFu, fia, s, 8);
        float ovb = __shfl_down_sync(0xFFFFFFFFu, fbb, s, 8);
        int   oib = __shfl_down_sync(0xFFFFFFFFu, fib, s, 8);
        if (ova < fba) { fba = ova; fia = oia; }
        if (ovb < fbb) { fbb = ovb; fib = oib; }
    }
    float pkf;
    if (r == 0) pkf = (float)wedge_peak(fia, fib, fxa, fxb) + EPSM;
    pkf = __shfl_sync(0xFFFFFFFFu, pkf, (t & ~7) & 31, 32);

    for (int i = r; i < ccnt; i += 8) {
        int k = scand[i];
        float m = smf[k], g = sgf[k];
        float vm = fminf(fmaf(m, fa, g), fmaf(m, fb, g));
        if (vm <= pkf) {
            int slot = atomicAdd(&sfcnt[j], 1);
            if (slot < FCAP) d_cand[fcell * FCAP + slot] = k;
        }
    }
    __syncthreads();

    // --- write fast table (one thread per fine cell) ---
    if (t < FPC) {
        int fc = cc * FPC + t;
        int cnt = sfcnt[t];
        float4 fv;
        if (cnt == 1) {
            int k = d_cand[fc * FCAP];          // written by this block; visible after syncthreads
            fv.x = smf[k]; fv.y = sgf[k]; fv.z = d_of[k];
        } else { fv.x = 0.f; fv.y = 0.f; fv.z = 0.f; }
        fv.w = __int_as_float(cnt);
        d_fast[fc] = fv;
    }
}

// ================= kB: pixels + fused deterministic final reduction =================
__device__ __forceinline__ void pix_one(float x, float bo, float Sw, float Swb, float Sb,
                                        float& res, double& lsum) {
    float rel = (x - (float)XLO) * (float)(1.0 / FWID);
    int cell = (int)floorf(rel);
    float bestf, oval;
    bool full = (cell < 0) || (cell >= NFINE);
    if (!full) {
        float4 f = d_fast[cell];
        int cnt = __float_as_int(f.w);
        if (cnt == 1) {
            bestf = fmaf(f.x, x, f.y);
            oval = f.z;
        } else if (cnt >= 2 && cnt <= FCAP) {
            double xd = (double)x;
            double best = 1e300;
            int bk = KC;
            int base = cell * FCAP;
            for (int i = 0; i < cnt; ++i) {
                int k = d_cand[base + i];
                double v = fma(d_m[k], xd, d_g[k]);
                if (v < best || (v == best && k < bk)) { best = v; bk = k; }
            }
            bestf = (float)best;
            oval = d_of[bk];
        } else full = true;
    }
    if (full) {
        double xd = (double)x;
        double best = 1e300;
        int bk = KC;
        for (int k = 0; k < KC; ++k) {
            double v = fma(d_m[k], xd, d_g[k]);
            if (v < best) { best = v; bk = k; }
        }
        bestf = (float)best;
        oval = d_of[bk];
    }
    res = oval + bo;
    lsum += (double)(bestf + fmaf(x, fmaf(x, Sw, 2.0f * Swb), Sb));
}

__global__ void __launch_bounds__(256) kB(const float4* __restrict__ x4,
                                          const float* __restrict__ b_out,
                                          float4* __restrict__ out4,
                                          float* __restrict__ out,
                                          int out_size) {
    __shared__ double sl[256];
    __shared__ int s_last;
    if (blockIdx.x == 0 && threadIdx.x == 0) d_barA = 0;   // re-arm kA's barrier

    int gid = blockIdx.x * 256 + threadIdx.x;
    float4 xv = x4[gid];
    float bo = b_out[0];
    float Sw = d_Swf, Swb = d_Swbf, Sb = d_Sbf;

    double lsum = 0.0;
    float4 ov;
    pix_one(xv.x, bo, Sw, Swb, Sb, ov.x, lsum);
    pix_one(xv.y, bo, Sw, Swb, Sb, ov.y, lsum);
    pix_one(xv.z, bo, Sw, Swb, Sb, ov.z, lsum);
    pix_one(xv.w, bo, Sw, Swb, Sb, ov.w, lsum);
    out4[gid] = ov;

    sl[threadIdx.x] = lsum;
    __syncthreads();
    for (int s = 128; s > 0; s >>= 1) {
        if (threadIdx.x < s) sl[threadIdx.x] += sl[threadIdx.x + s];
        __syncthreads();
    }
    if (threadIdx.x == 0) {
        d_bsum[blockIdx.x] = sl[0];
        __threadfence();
        unsigned v = atomicAdd(&d_doneB, 1);
        s_last = (v == NBLKB - 1);
    }
    __syncthreads();

    if (s_last) {
        // last block: deterministic fixed-order reduction of 256 partials
        __threadfence();
        sl[threadIdx.x] = d_bsum[threadIdx.x];
        __syncthreads();
        for (int s = 128; s > 0; s >>= 1) {
            if (threadIdx.x < s) sl[threadIdx.x] += sl[threadIdx.x + s];
            __syncthreads();
        }
        if (threadIdx.x == 0 && out_size > NPIX) {
            // loss = KLD*(CC+1)*mean = 12.5 * sum / (NPIX*D)
            out[NPIX] = (float)(12.5 * sl[0] / ((double)NPIX * (double)DIMD));
        }
    }
}

extern "C" void kernel_launch(void* const* d_in, const int* in_sizes, int n_in,
                              void* d_out, int out_size) {
    const float* x     = (const float*)d_in[0];
    const float* w_in  = (const float*)d_in[1];
    const float* b_in  = (const float*)d_in[2];
    const float* emb   = (const float*)d_in[3];
    const float* w_out = (const float*)d_in[4];
    const float* b_out = (const float*)d_in[5];
    float* out = (float*)d_out;

    kA<<<NCOARSE, 256>>>(emb, w_in, b_in, w_out);
    kB<<<NBLKB, 256>>>((const float4*)x, b_out, (float4*)out, out, out_size);
}